// round 2
// baseline (speedup 1.0000x reference)
#include <cuda_runtime.h>
#include <math.h>

// ---------------------------------------------------------------------------
// TCVAE loss — single-launch fused version.
//
// Algebra (ALPHA=BETA=GAMMA=1): the O(B^2*D) pairwise logsumexp terms
// telescope away:
//   kl_loss = mean(log q(z|x)) - mean(log p(z))
// Remaining:
//   recon_loss = sum |x - recon| / (B*T)
//   kl_loss    = (1/B) * sum_{i,d} [ -0.5*((z-mu)^2*e^{-lv} + lv)
//                                    +0.5*( z^2*e^{-1}      + 1 ) ]
// (log(2*pi) cancels elementwise.)
//
// Single kernel: block partials -> device slots (written, never accumulated,
// so no zero-init launch), ticket counter, last block finalizes and resets
// the ticket => idempotent across CUDA-graph replays.
// ---------------------------------------------------------------------------

#define GRID_BLOCKS 1024
#define BLOCK_THREADS 256

__device__ float2 g_partials[GRID_BLOCKS];
__device__ unsigned int g_ticket = 0;

__global__ void __launch_bounds__(BLOCK_THREADS) tcvae_fused_kernel(
    const float4* __restrict__ recon4,
    const float4* __restrict__ x4,
    int n_bt4,                       // (B*T)/4
    const float4* __restrict__ mu4,
    const float4* __restrict__ lv4,
    const float4* __restrict__ z4,
    int n_bd4,                       // (B*D)/4
    float* __restrict__ out,
    int n_bt, int batch)
{
    const float INV_E = 0.36787944117144233f;  // e^{-1}

    float racc = 0.0f;
    float kacc = 0.0f;

    int tid = blockIdx.x * BLOCK_THREADS + threadIdx.x;
    int stride = GRID_BLOCKS * BLOCK_THREADS;

    // reconstruction L1 term
    for (int i = tid; i < n_bt4; i += stride) {
        float4 a = recon4[i];
        float4 b = x4[i];
        racc += fabsf(b.x - a.x) + fabsf(b.y - a.y)
              + fabsf(b.z - a.z) + fabsf(b.w - a.w);
    }

    // KL term: gauss(z; mu, lv) - gauss(z; 0, 1)
    for (int i = tid; i < n_bd4; i += stride) {
        float4 m = mu4[i];
        float4 l = lv4[i];
        float4 s = z4[i];
        float t;
        t = s.x - m.x; kacc += -0.5f * (t*t*expf(-l.x) + l.x) + 0.5f * (s.x*s.x*INV_E + 1.0f);
        t = s.y - m.y; kacc += -0.5f * (t*t*expf(-l.y) + l.y) + 0.5f * (s.y*s.y*INV_E + 1.0f);
        t = s.z - m.z; kacc += -0.5f * (t*t*expf(-l.z) + l.z) + 0.5f * (s.z*s.z*INV_E + 1.0f);
        t = s.w - m.w; kacc += -0.5f * (t*t*expf(-l.w) + l.w) + 0.5f * (s.w*s.w*INV_E + 1.0f);
    }

    // ---- block reduction ----
    #pragma unroll
    for (int o = 16; o > 0; o >>= 1) {
        racc += __shfl_xor_sync(0xFFFFFFFFu, racc, o);
        kacc += __shfl_xor_sync(0xFFFFFFFFu, kacc, o);
    }

    __shared__ float sr[BLOCK_THREADS / 32];
    __shared__ float sk[BLOCK_THREADS / 32];
    int lane = threadIdx.x & 31;
    int warp = threadIdx.x >> 5;
    if (lane == 0) { sr[warp] = racc; sk[warp] = kacc; }
    __syncthreads();

    if (warp == 0) {
        racc = (lane < (BLOCK_THREADS / 32)) ? sr[lane] : 0.0f;
        kacc = (lane < (BLOCK_THREADS / 32)) ? sk[lane] : 0.0f;
        #pragma unroll
        for (int o = 4; o > 0; o >>= 1) {
            racc += __shfl_xor_sync(0xFFFFFFFFu, racc, o);
            kacc += __shfl_xor_sync(0xFFFFFFFFu, kacc, o);
        }
        if (lane == 0) g_partials[blockIdx.x] = make_float2(racc, kacc);
    }

    // ---- last-block-done finalize ----
    __threadfence();
    __shared__ bool is_last;
    if (threadIdx.x == 0) {
        unsigned int t = atomicAdd(&g_ticket, 1u);
        is_last = (t == (unsigned int)(GRID_BLOCKS - 1));
    }
    __syncthreads();

    if (is_last) {
        float r = 0.0f, k = 0.0f;
        for (int i = threadIdx.x; i < GRID_BLOCKS; i += BLOCK_THREADS) {
            float2 p = g_partials[i];
            r += p.x;
            k += p.y;
        }
        #pragma unroll
        for (int o = 16; o > 0; o >>= 1) {
            r += __shfl_xor_sync(0xFFFFFFFFu, r, o);
            k += __shfl_xor_sync(0xFFFFFFFFu, k, o);
        }
        __shared__ double dr[BLOCK_THREADS / 32];
        __shared__ double dk[BLOCK_THREADS / 32];
        if (lane == 0) { dr[warp] = (double)r; dk[warp] = (double)k; }
        __syncthreads();
        if (threadIdx.x == 0) {
            double rs = 0.0, ks = 0.0;
            #pragma unroll
            for (int w = 0; w < BLOCK_THREADS / 32; w++) { rs += dr[w]; ks += dk[w]; }
            float recon_loss = (float)(rs / (double)n_bt);
            float kl_loss    = (float)(ks / (double)batch);
            out[0] = recon_loss + kl_loss;
            out[1] = recon_loss;
            out[2] = kl_loss;
            g_ticket = 0;  // reset for next graph replay (idempotent)
        }
    }
}

extern "C" void kernel_launch(void* const* d_in, const int* in_sizes, int n_in,
                              void* d_out, int out_size) {
    const float* recon   = (const float*)d_in[0];  // [B, T]
    const float* x       = (const float*)d_in[1];  // [B, T]
    const float* mu      = (const float*)d_in[2];  // [B, D]
    const float* log_var = (const float*)d_in[3];  // [B, D]
    const float* z       = (const float*)d_in[4];  // [B, D]
    // d_in[5] = dataset_size: unused (telescoping cancellation).

    int n_bt = in_sizes[0];          // B*T = 1048576
    int n_bd = in_sizes[2];          // B*D = 65536
    const int batch = 2048;          // B

    tcvae_fused_kernel<<<GRID_BLOCKS, BLOCK_THREADS>>>(
        (const float4*)recon, (const float4*)x, n_bt / 4,
        (const float4*)mu, (const float4*)log_var, (const float4*)z, n_bd / 4,
        (float*)d_out, n_bt, batch);
}

// round 3
// speedup vs baseline: 1.2684x; 1.2684x over previous
#include <cuda_runtime.h>
#include <math.h>

// ---------------------------------------------------------------------------
// TCVAE loss — single-launch, latency-optimized.
//
// Algebra (ALPHA=BETA=GAMMA=1): the O(B^2*D) pairwise logsumexp terms
// telescope away:  kl_loss = mean(log q(z|x)) - mean(log p(z)).
// Remaining:
//   recon_loss = sum |x - recon| / (B*T)
//   kl_loss    = (1/B) * sum_{i,d} [ -0.5*((z-mu)^2*e^{-lv} + lv)
//                                    +0.5*( z^2*e^{-1}      + 1 ) ]
//
// vs round 2: no __threadfence (acq_rel ticket atomic instead), 256 blocks
// x 512 threads with unroll-2 front-batched loads (MLP_p1~4), smaller tail.
// ---------------------------------------------------------------------------

#define GRID_BLOCKS 256
#define BLOCK_THREADS 512
#define NWARPS (BLOCK_THREADS / 32)

__device__ float2 g_partials[GRID_BLOCKS];
__device__ unsigned int g_ticket = 0;

__global__ void __launch_bounds__(BLOCK_THREADS) tcvae_fused_kernel(
    const float4* __restrict__ recon4,
    const float4* __restrict__ x4,
    int n_bt4,                       // (B*T)/4 = 262144
    const float4* __restrict__ mu4,
    const float4* __restrict__ lv4,
    const float4* __restrict__ z4,
    int n_bd4,                       // (B*D)/4 = 16384
    float* __restrict__ out,
    int n_bt, int batch)
{
    const float INV_E = 0.36787944117144233f;  // e^{-1}

    float racc = 0.0f;
    float kacc = 0.0f;

    int tid = blockIdx.x * BLOCK_THREADS + threadIdx.x;
    int stride = GRID_BLOCKS * BLOCK_THREADS;   // 131072

    // KL term first (tiny; loads issue early and overlap the recon stream)
    for (int i = tid; i < n_bd4; i += stride) {
        float4 m = mu4[i];
        float4 l = lv4[i];
        float4 s = z4[i];
        float t;
        t = s.x - m.x; kacc += -0.5f * (t*t*__expf(-l.x) + l.x) + 0.5f * (s.x*s.x*INV_E + 1.0f);
        t = s.y - m.y; kacc += -0.5f * (t*t*__expf(-l.y) + l.y) + 0.5f * (s.y*s.y*INV_E + 1.0f);
        t = s.z - m.z; kacc += -0.5f * (t*t*__expf(-l.z) + l.z) + 0.5f * (s.z*s.z*INV_E + 1.0f);
        t = s.w - m.w; kacc += -0.5f * (t*t*__expf(-l.w) + l.w) + 0.5f * (s.w*s.w*INV_E + 1.0f);
    }

    // reconstruction L1 term, unroll-2 so 4 independent LDG.128 batch up front
    {
        int i = tid;
        for (; i + stride < n_bt4; i += 2 * stride) {
            float4 a0 = recon4[i];
            float4 a1 = recon4[i + stride];
            float4 b0 = x4[i];
            float4 b1 = x4[i + stride];
            racc += fabsf(b0.x - a0.x) + fabsf(b0.y - a0.y)
                  + fabsf(b0.z - a0.z) + fabsf(b0.w - a0.w);
            racc += fabsf(b1.x - a1.x) + fabsf(b1.y - a1.y)
                  + fabsf(b1.z - a1.z) + fabsf(b1.w - a1.w);
        }
        for (; i < n_bt4; i += stride) {
            float4 a = recon4[i];
            float4 b = x4[i];
            racc += fabsf(b.x - a.x) + fabsf(b.y - a.y)
                  + fabsf(b.z - a.z) + fabsf(b.w - a.w);
        }
    }

    // ---- block reduction ----
    #pragma unroll
    for (int o = 16; o > 0; o >>= 1) {
        racc += __shfl_xor_sync(0xFFFFFFFFu, racc, o);
        kacc += __shfl_xor_sync(0xFFFFFFFFu, kacc, o);
    }

    __shared__ float sr[NWARPS];
    __shared__ float sk[NWARPS];
    int lane = threadIdx.x & 31;
    int warp = threadIdx.x >> 5;
    if (lane == 0) { sr[warp] = racc; sk[warp] = kacc; }
    __syncthreads();

    __shared__ bool is_last;
    if (warp == 0) {
        racc = (lane < NWARPS) ? sr[lane] : 0.0f;
        kacc = (lane < NWARPS) ? sk[lane] : 0.0f;
        #pragma unroll
        for (int o = 8; o > 0; o >>= 1) {
            racc += __shfl_xor_sync(0xFFFFFFFFu, racc, o);
            kacc += __shfl_xor_sync(0xFFFFFFFFu, kacc, o);
        }
        if (lane == 0) {
            g_partials[blockIdx.x] = make_float2(racc, kacc);
            // acq_rel atomic: release makes the partial store visible before
            // the ticket bump; acquire lets the last block read all partials.
            unsigned int t;
            asm volatile("atom.acq_rel.gpu.global.add.u32 %0, [%1], 1;"
                         : "=r"(t) : "l"(&g_ticket) : "memory");
            is_last = (t == (unsigned int)(GRID_BLOCKS - 1));
        }
    }
    __syncthreads();

    // ---- last-block finalize (one 2KB read, single round trip) ----
    if (is_last) {
        float r = 0.0f, k = 0.0f;
        if (threadIdx.x < GRID_BLOCKS) {
            float2 p = g_partials[threadIdx.x];
            r = p.x;
            k = p.y;
        }
        #pragma unroll
        for (int o = 16; o > 0; o >>= 1) {
            r += __shfl_xor_sync(0xFFFFFFFFu, r, o);
            k += __shfl_xor_sync(0xFFFFFFFFu, k, o);
        }
        __shared__ double dr[NWARPS];
        __shared__ double dk[NWARPS];
        if (lane == 0) { dr[warp] = (double)r; dk[warp] = (double)k; }
        __syncthreads();
        if (threadIdx.x == 0) {
            double rs = 0.0, ks = 0.0;
            #pragma unroll
            for (int w = 0; w < GRID_BLOCKS / 32; w++) { rs += dr[w]; ks += dk[w]; }
            float recon_loss = (float)(rs / (double)n_bt);
            float kl_loss    = (float)(ks / (double)batch);
            out[0] = recon_loss + kl_loss;
            out[1] = recon_loss;
            out[2] = kl_loss;
            g_ticket = 0;  // reset for next graph replay (idempotent)
        }
    }
}

extern "C" void kernel_launch(void* const* d_in, const int* in_sizes, int n_in,
                              void* d_out, int out_size) {
    const float* recon   = (const float*)d_in[0];  // [B, T]
    const float* x       = (const float*)d_in[1];  // [B, T]
    const float* mu      = (const float*)d_in[2];  // [B, D]
    const float* log_var = (const float*)d_in[3];  // [B, D]
    const float* z       = (const float*)d_in[4];  // [B, D]
    // d_in[5] = dataset_size: unused (telescoping cancellation).

    int n_bt = in_sizes[0];          // B*T = 1048576
    int n_bd = in_sizes[2];          // B*D = 65536
    const int batch = 2048;          // B

    tcvae_fused_kernel<<<GRID_BLOCKS, BLOCK_THREADS>>>(
        (const float4*)recon, (const float4*)x, n_bt / 4,
        (const float4*)mu, (const float4*)log_var, (const float4*)z, n_bd / 4,
        (float*)d_out, n_bt, batch);
}